// round 7
// baseline (speedup 1.0000x reference)
#include <cuda_runtime.h>
#include <math.h>

#define D_MODEL   3072
#define NUM_E     8
#define N_TOKENS  16384
#define TPW       4                       // tokens per warp-quad
#define WARPS_PB  16
#define THREADS   (WARPS_PB * 32)         // 512
#define CHUNK_D   128                     // floats of D per pipeline stage
#define NCHUNK    (D_MODEL / CHUNK_D)     // 24
#define NSTAGE    4                       // per-warp ring depth
#define GRID      148
#define NWARPS_G  (GRID * WARPS_PB)       // 2368
#define NQUADS    (N_TOKENS / TPW)        // 4096
#define ROW_V     (D_MODEL / 4)           // 768 16B elems per W row
#define RING_FLOATS_PER_WARP (NSTAGE * TPW * CHUNK_D)    // 2048 floats = 8 KB
#define SMEM_BYTES ((NUM_E * D_MODEL + WARPS_PB * RING_FLOATS_PER_WARP) * 4)  // 224 KB

typedef unsigned long long u64;

__device__ __forceinline__ u64 ffma2(u64 a, u64 b, u64 c) {
    u64 d;
    asm("fma.rn.f32x2 %0, %1, %2, %3;" : "=l"(d) : "l"(a), "l"(b), "l"(c));
    return d;
}
__device__ __forceinline__ float unpack_sum(u64 v) {
    return __uint_as_float((unsigned)(v & 0xFFFFFFFFull)) +
           __uint_as_float((unsigned)(v >> 32));
}

__global__ void __launch_bounds__(THREADS, 1)
gating_kernel(const float* __restrict__ x,
              const float* __restrict__ W,
              const float* __restrict__ b,
              float* __restrict__ out,
              int idx_off)
{
    extern __shared__ float smem[];
    float* sW = smem;                                   // [8][3072]
    float* sX = smem + NUM_E * D_MODEL;                 // per-warp rings

    {
        const float4* Wv = reinterpret_cast<const float4*>(W);
        float4* sWv4 = reinterpret_cast<float4*>(sW);
        #pragma unroll 4
        for (int i = threadIdx.x; i < NUM_E * D_MODEL / 4; i += THREADS)
            sWv4[i] = Wv[i];
    }

    const int warp = threadIdx.x >> 5;
    const int lane = threadIdx.x & 31;
    const int bid  = blockIdx.x;

    // Preload bias into registers (tiny, L1-hit after first warp).
    float bias[NUM_E];
    #pragma unroll
    for (int e = 0; e < NUM_E; ++e) bias[e] = __ldg(&b[e]);

    __syncthreads();

    float* ring = sX + warp * RING_FLOATS_PER_WARP;
    const unsigned ring_s =
        (unsigned)__cvta_generic_to_shared(ring) + lane * 16;
    const ulonglong2* __restrict__ ringv =
        reinterpret_cast<const ulonglong2*>(ring);
    const ulonglong2* __restrict__ sWv =
        reinterpret_cast<const ulonglong2*>(sW);

    // Persistent: quads q0 and (maybe) q0 + 2368.
    const int q0 = bid + GRID * warp;                 // < 2368
    const int nq = (q0 + NWARPS_G < NQUADS) ? 2 : 1;
    const int T  = nq * NCHUNK;

    // stage t -> quad j = t/24, chunk c = t%24, ring slot t%4
    #define ISSUE_STAGE(t_)                                                   \
        do {                                                                  \
            int _t = (t_);                                                    \
            int _j = _t / NCHUNK;                                             \
            int _c = _t - _j * NCHUNK;                                        \
            const float* _src = x + (size_t)(q0 + _j * NWARPS_G)              \
                                    * (TPW * D_MODEL)                         \
                                  + _c * CHUNK_D + lane * 4;                  \
            unsigned _dst = ring_s + (_t % NSTAGE) * (TPW * CHUNK_D * 4);     \
            _Pragma("unroll")                                                 \
            for (int _tt = 0; _tt < TPW; ++_tt)                               \
                asm volatile("cp.async.cg.shared.global [%0], [%1], 16;"      \
                             :: "r"(_dst + _tt * (CHUNK_D * 4)),              \
                                "l"(_src + (size_t)_tt * D_MODEL));           \
        } while (0)

    u64 acc[TPW][NUM_E];
    #pragma unroll
    for (int t = 0; t < TPW; ++t)
        #pragma unroll
        for (int e = 0; e < NUM_E; ++e)
            acc[t][e] = 0ull;

    // Prologue: stages 0,1,2 committed; wait for stage 0; preload xcur.
    ISSUE_STAGE(0);
    asm volatile("cp.async.commit_group;" ::: "memory");
    ISSUE_STAGE(1);
    asm volatile("cp.async.commit_group;" ::: "memory");
    ISSUE_STAGE(2);
    asm volatile("cp.async.commit_group;" ::: "memory");
    asm volatile("cp.async.wait_group 2;" ::: "memory");

    ulonglong2 xcur[TPW], xnxt[TPW];
    #pragma unroll
    for (int tt = 0; tt < TPW; ++tt)
        xcur[tt] = ringv[tt * (CHUNK_D / 4) + lane];   // slot 0

    for (int t = 0; t < T; ++t) {
        // Keep 3 stages committed.
        if (t + 3 < T) {
            ISSUE_STAGE(t + 3);
            asm volatile("cp.async.commit_group;" ::: "memory");
            // pending: t+1..t+3 -> keep 2 newest => stage t+1 complete
            asm volatile("cp.async.wait_group 2;" ::: "memory");
        } else {
            asm volatile("cp.async.wait_group 0;" ::: "memory");
        }

        // Prefetch next stage's x into registers BEFORE the FFMA block,
        // so LDS latency hides behind the 64 FFMA2s below.
        if (t + 1 < T) {
            const ulonglong2* xs =
                ringv + ((t + 1) % NSTAGE) * (TPW * CHUNK_D / 4);
            #pragma unroll
            for (int tt = 0; tt < TPW; ++tt)
                xnxt[tt] = xs[tt * (CHUNK_D / 4) + lane];
        }

        const int j = t / NCHUNK;
        const int c = t - j * NCHUNK;

        #pragma unroll
        for (int e = 0; e < NUM_E; ++e) {
            const ulonglong2 wv = sWv[e * ROW_V + c * (CHUNK_D / 4) + lane];
            #pragma unroll
            for (int tt = 0; tt < TPW; ++tt) {
                acc[tt][e] = ffma2(xcur[tt].x, wv.x, acc[tt][e]);
                acc[tt][e] = ffma2(xcur[tt].y, wv.y, acc[tt][e]);
            }
        }

        #pragma unroll
        for (int tt = 0; tt < TPW; ++tt)
            xcur[tt] = xnxt[tt];

        if (c == NCHUNK - 1) {
            // ---- epilogue for quad q = q0 + j*NWARPS_G ----
            const int tok0 = (q0 + j * NWARPS_G) * TPW;

            float red[TPW][NUM_E];
            #pragma unroll
            for (int tt = 0; tt < TPW; ++tt)
                #pragma unroll
                for (int e = 0; e < NUM_E; ++e) {
                    red[tt][e] = unpack_sum(acc[tt][e]);
                    acc[tt][e] = 0ull;
                }

            #pragma unroll
            for (int off = 16; off > 0; off >>= 1)
                #pragma unroll
                for (int tt = 0; tt < TPW; ++tt)
                    #pragma unroll
                    for (int e = 0; e < NUM_E; ++e)
                        red[tt][e] += __shfl_xor_sync(0xFFFFFFFFu, red[tt][e], off);

            if (lane < TPW) {
                const int tok = tok0 + lane;

                float logit[NUM_E];
                #pragma unroll
                for (int e = 0; e < NUM_E; ++e)
                    logit[e] = red[lane][e] + bias[e];

                float m = logit[0];
                #pragma unroll
                for (int e = 1; e < NUM_E; ++e) m = fmaxf(m, logit[e]);

                float ex[NUM_E], Z = 0.0f;
                #pragma unroll
                for (int e = 0; e < NUM_E; ++e) { ex[e] = __expf(logit[e] - m); Z += ex[e]; }
                const float invZ = 1.0f / Z;

                float sc[NUM_E];
                #pragma unroll
                for (int e = 0; e < NUM_E; ++e) sc[e] = ex[e] * invZ;

                int i1 = 0;
                #pragma unroll
                for (int e = 1; e < NUM_E; ++e) if (sc[e] > sc[i1]) i1 = e;
                int i2 = (i1 == 0) ? 1 : 0;
                #pragma unroll
                for (int e = 0; e < NUM_E; ++e)
                    if (e != i1 && sc[e] > sc[i2]) i2 = e;

                const float v1 = sc[i1];
                const float v2 = sc[i2];
                const float e2 = __expf(v2 - v1);
                const float r1 = 1.0f / (1.0f + e2);
                const float r2 = 1.0f - r1;

                out[(size_t)tok * 2 + 0] = r1;
                out[(size_t)tok * 2 + 1] = r2;
                out[(size_t)idx_off + (size_t)tok * 2 + 0] = (float)i1;
                out[(size_t)idx_off + (size_t)tok * 2 + 1] = (float)i2;
            }
        }
    }
    #undef ISSUE_STAGE
}

extern "C" void kernel_launch(void* const* d_in, const int* in_sizes, int n_in,
                              void* d_out, int out_size)
{
    const float* x = (const float*)d_in[0];
    const float* W = (const float*)d_in[1];
    const float* b = (const float*)d_in[2];
    float* out = (float*)d_out;

    const int idx_off = out_size / 2;

    cudaFuncSetAttribute(gating_kernel,
                         cudaFuncAttributeMaxDynamicSharedMemorySize,
                         (int)SMEM_BYTES);

    gating_kernel<<<GRID, THREADS, SMEM_BYTES>>>(x, W, b, out, idx_off);
}